// round 8
// baseline (speedup 1.0000x reference)
#include <cuda_runtime.h>

#define NUSERS  100000
#define NNODES  300000
#define NEDGES  1250000
#define HID     64
#define EIG     16
#define NPATHS  14
#define LN_EPS  1e-5f

#define SCAN_BLK 1024
#define NBLK1    ((NNODES + SCAN_BLK - 1) / SCAN_BLK)   // 293

// ---------------- scratch (device globals: no allocation allowed) ----------
__device__ float g_yA[(size_t)NNODES * HID];     // layer-0 layernormed emb
__device__ float g_yB[(size_t)NNODES * HID];     // layer-1 layernormed emb
__device__ int   g_ecol[NEDGES];                 // col | (pt<<19), sorted by row
__device__ int   g_count[NNODES];                // row degree
__device__ int   g_off[NNODES];                  // CSR row offsets
__device__ int   g_cursor[NNODES];               // scatter cursors
__device__ int   g_total;                        // scan base allocator

// ------------------------------ CSR build ----------------------------------
__global__ void k_zero() {
    int i = blockIdx.x * blockDim.x + threadIdx.x;
    if (i < NNODES) g_count[i] = 0;
    if (i == 0) g_total = 0;
}

__global__ void k_count(const int* __restrict__ idx) {
    int e = blockIdx.x * blockDim.x + threadIdx.x;
    if (e < NEDGES) atomicAdd(&g_count[idx[e]], 1);
}

__device__ __forceinline__ int block_incl_scan(int v, int* ws) {
    int lane = threadIdx.x & 31, wid = threadIdx.x >> 5;
    int x = v;
    #pragma unroll
    for (int o = 1; o < 32; o <<= 1) {
        int t = __shfl_up_sync(0xFFFFFFFFu, x, o);
        if (lane >= o) x += t;
    }
    if (lane == 31) ws[wid] = x;
    __syncthreads();
    if (wid == 0) {
        int y = (lane < (blockDim.x >> 5)) ? ws[lane] : 0;
        #pragma unroll
        for (int o = 1; o < 32; o <<= 1) {
            int t = __shfl_up_sync(0xFFFFFFFFu, y, o);
            if (lane >= o) y += t;
        }
        ws[lane] = y;
    }
    __syncthreads();
    return x + (wid ? ws[wid - 1] : 0);
}

// Block-local scan + atomic base grab: CSR only needs disjoint contiguous
// slices per row, not globally ordered offsets.
__global__ void k_scan() {
    __shared__ int ws[32];
    __shared__ int s_base;
    int gid = blockIdx.x * SCAN_BLK + threadIdx.x;
    int v = (gid < NNODES) ? g_count[gid] : 0;
    int incl = block_incl_scan(v, ws);
    if (threadIdx.x == SCAN_BLK - 1) s_base = atomicAdd(&g_total, incl);
    __syncthreads();
    if (gid < NNODES) {
        int o = s_base + incl - v;
        g_off[gid]    = o;
        g_cursor[gid] = o;
    }
}

__global__ void k_scatter(const int* __restrict__ idx,
                          const int* __restrict__ ptype) {
    int e = blockIdx.x * blockDim.x + threadIdx.x;
    if (e >= NEDGES) return;
    int row = idx[e];
    int pos = atomicAdd(&g_cursor[row], 1);
    g_ecol[pos] = idx[NEDGES + e] | (ptype[e] << 19);   // col < 2^19, pt < 16
}

// ---------------------------------------------------------------------------
// Layer-0 layernorm: half-warp per row, float4 lanes.
//   g_yA = LN(concat(ue, ie));  out = concat(ue, ie)   (emb0 seed)
__global__ void __launch_bounds__(256) k_ln0(const float* __restrict__ ue,
                                             const float* __restrict__ ie,
                                             float* __restrict__ out) {
    int tid  = blockIdx.x * blockDim.x + threadIdx.x;
    int row  = tid >> 4;
    int lane = threadIdx.x & 15;
    if (row >= NNODES) return;

    const float* src = (row < NUSERS)
        ? ue + (size_t)row * HID
        : ie + (size_t)(row - NUSERS) * HID;
    float4 v = ((const float4*)src)[lane];

    float s  = v.x + v.y + v.z + v.w;
    float sq = v.x * v.x + v.y * v.y + v.z * v.z + v.w * v.w;
    #pragma unroll
    for (int o = 8; o; o >>= 1) {
        s  += __shfl_xor_sync(0xFFFFFFFFu, s,  o);
        sq += __shfl_xor_sync(0xFFFFFFFFu, sq, o);
    }
    float mu  = s * (1.0f / HID);
    float var = sq * (1.0f / HID) - mu * mu;
    float r   = rsqrtf(var + LN_EPS);

    float4 o4;
    o4.x = (v.x - mu) * r;
    o4.y = (v.y - mu) * r;
    o4.z = (v.z - mu) * r;
    o4.w = (v.w - mu) * r;
    ((float4*)(g_yA + (size_t)row * HID))[lane] = o4;
    ((float4*)(out  + (size_t)row * HID))[lane] = v;
}

// ---------------------------------------------------------------------------
// Fused single-pass attention, half-warp per row, atomic-free.
// Uses linearity of the output in the softmax numerators:
//   res = 0.5*(Σ e0·y[c])/Σe0 + 0.5*(Σ ep·y[c])/Σep
// so each y[c] row is gathered exactly ONCE. (Softmax max-shift dropped:
// ratio is shift-invariant; magnitudes f32-safe for these distributions.)
//   final==0 : out += res (emb1 accumulate);  ydst = LN(res) for next layer
//   final==1 : out = (out + res) / 3
__global__ void __launch_bounds__(256) k_attn(const float* __restrict__ ysrc,
                                              float* __restrict__ ydst,
                                              const float* __restrict__ eigs,
                                              const float* __restrict__ lam_l,
                                              const float* __restrict__ pemb,
                                              float* __restrict__ out,
                                              int final_mode) {
    __shared__ float s_ep[NPATHS];
    if (threadIdx.x < NPATHS) s_ep[threadIdx.x] = expf(pemb[threadIdx.x]);
    __syncthreads();

    int tid  = blockIdx.x * blockDim.x + threadIdx.x;
    int row  = tid >> 4;
    int lane = threadIdx.x & 15;
    if (row >= NNODES) return;

    int start = g_off[row];
    int deg   = g_count[row];

    float4 yr = ((const float4*)(ysrc + (size_t)row * HID))[lane];
    float  er = eigs[(size_t)row * EIG + lane];       // EIG == 16 lanes
    float  elam = expf(lam_l[0]) * er;                // fold er in

    float4 acc0 = make_float4(0.f, 0.f, 0.f, 0.f);
    float4 acc1 = make_float4(0.f, 0.f, 0.f, 0.f);
    float  den0 = 0.0f, den1 = 0.0f;

    for (int pos = start; pos < start + deg; ++pos) {
        int packed = g_ecol[pos];                     // broadcast load
        int c  = packed & 0x7FFFF;
        int ptv = packed >> 19;
        float4 yc = ((const float4*)(ysrc + (size_t)c * HID))[lane];
        float  ec = eigs[(size_t)c * EIG + lane];
        float part = (yr.x * yc.x + yr.y * yc.y + yr.z * yc.z + yr.w * yc.w) * 0.125f
                   + elam * ec;
        #pragma unroll
        for (int o = 8; o; o >>= 1)
            part += __shfl_xor_sync(0xFFFFFFFFu, part, o);
        float e0 = expf(part);                        // same on all 16 lanes
        float ep = s_ep[ptv];
        den0 += e0;  den1 += ep;
        acc0.x += e0 * yc.x;  acc0.y += e0 * yc.y;
        acc0.z += e0 * yc.z;  acc0.w += e0 * yc.w;
        acc1.x += ep * yc.x;  acc1.y += ep * yc.y;
        acc1.z += ep * yc.z;  acc1.w += ep * yc.w;
    }

    float4 res = make_float4(0.f, 0.f, 0.f, 0.f);
    if (deg > 0) {
        float i0 = 0.5f / den0;
        float i1 = 0.5f / den1;
        res.x = acc0.x * i0 + acc1.x * i1;
        res.y = acc0.y * i0 + acc1.y * i1;
        res.z = acc0.z * i0 + acc1.z * i1;
        res.w = acc0.w * i0 + acc1.w * i1;
    }

    float4* op = (float4*)(out + (size_t)row * HID);
    if (final_mode) {
        float4 cur = op[lane];
        cur.x = (cur.x + res.x) * (1.0f / 3.0f);
        cur.y = (cur.y + res.y) * (1.0f / 3.0f);
        cur.z = (cur.z + res.z) * (1.0f / 3.0f);
        cur.w = (cur.w + res.w) * (1.0f / 3.0f);
        op[lane] = cur;
    } else {
        // out += emb1
        float4 cur = op[lane];
        cur.x += res.x; cur.y += res.y; cur.z += res.z; cur.w += res.w;
        op[lane] = cur;

        // layernorm res -> ydst (next layer's y), race-free (separate buffer)
        float s  = res.x + res.y + res.z + res.w;
        float sq = res.x * res.x + res.y * res.y + res.z * res.z + res.w * res.w;
        #pragma unroll
        for (int o = 8; o; o >>= 1) {
            s  += __shfl_xor_sync(0xFFFFFFFFu, s,  o);
            sq += __shfl_xor_sync(0xFFFFFFFFu, sq, o);
        }
        float mu  = s * (1.0f / HID);
        float var = sq * (1.0f / HID) - mu * mu;
        float rr  = rsqrtf(var + LN_EPS);
        float4 o4;
        o4.x = (res.x - mu) * rr;
        o4.y = (res.y - mu) * rr;
        o4.z = (res.z - mu) * rr;
        o4.w = (res.w - mu) * rr;
        ((float4*)(ydst + (size_t)row * HID))[lane] = o4;
    }
}

// ---------------------------------------------------------------------------
extern "C" void kernel_launch(void* const* d_in, const int* in_sizes, int n_in,
                              void* d_out, int out_size) {
    const float* ue   = (const float*)d_in[0];
    const float* ie   = (const float*)d_in[1];
    const float* eigs = (const float*)d_in[2];
    const float* lam  = (const float*)d_in[3];
    const float* pw   = (const float*)d_in[4];
    const int*   idx  = (const int*)d_in[5];
    const int*   pt   = (const int*)d_in[6];
    float*       out  = (float*)d_out;

    float *yA, *yB;
    cudaGetSymbolAddress((void**)&yA, g_yA);
    cudaGetSymbolAddress((void**)&yB, g_yB);

    const int edge_grid = (NEDGES + 255) / 256;
    const int node_grid = (NNODES + 255) / 256;
    const int half_grid = ((NNODES * 16) + 255) / 256;   // half-warp per row

    // CSR build (shared by both layers)
    k_zero   <<<node_grid, 256>>>();
    k_count  <<<edge_grid, 256>>>(idx);
    k_scan   <<<NBLK1, SCAN_BLK>>>();
    k_scatter<<<edge_grid, 256>>>(idx, pt);

    // layer 0: yA -> attn (out += emb1, yB = LN(emb1))
    k_ln0 <<<half_grid, 256>>>(ue, ie, out);
    k_attn<<<half_grid, 256>>>(yA, yB, eigs, lam + 0, pw + 0 * NPATHS, out, 0);

    // layer 1: yB -> attn -> out = (out + emb2)/3
    k_attn<<<half_grid, 256>>>(yB, yA, eigs, lam + 1, pw + 1 * NPATHS, out, 1);
}

// round 9
// speedup vs baseline: 1.1130x; 1.1130x over previous
#include <cuda_runtime.h>

#define NUSERS  100000
#define NNODES  300000
#define NEDGES  1250000
#define HID     64
#define EIG     16
#define NPATHS  14
#define LN_EPS  1e-5f

#define SCAN_BLK 1024
#define NBLK1    ((NNODES + SCAN_BLK - 1) / SCAN_BLK)   // 293

// ---------------- scratch (device globals: no allocation allowed) ----------
__device__ float g_yA[(size_t)NNODES * HID];     // layernormed emb (layer 0)
__device__ float g_yB[(size_t)NNODES * HID];     // layernormed emb (layer 1)
__device__ int   g_erow[NEDGES];                 // row per sorted edge
__device__ int   g_ecol[NEDGES];                 // col | (pt<<19), sorted by row
__device__ float g_e0[NEDGES];                   // exp(s0) per sorted edge
__device__ int   g_count[NNODES];                // row degree
__device__ int   g_off[NNODES];                  // CSR row offsets
__device__ int   g_cursor[NNODES];               // scatter cursors
__device__ int   g_total;                        // scan base allocator

// ------------------------------ CSR build ----------------------------------
__global__ void k_zero() {
    int i = blockIdx.x * blockDim.x + threadIdx.x;
    if (i < NNODES) g_count[i] = 0;
    if (i == 0) g_total = 0;
}

__global__ void k_count(const int* __restrict__ idx) {
    int e = blockIdx.x * blockDim.x + threadIdx.x;
    if (e < NEDGES) atomicAdd(&g_count[idx[e]], 1);
}

__device__ __forceinline__ int block_incl_scan(int v, int* ws) {
    int lane = threadIdx.x & 31, wid = threadIdx.x >> 5;
    int x = v;
    #pragma unroll
    for (int o = 1; o < 32; o <<= 1) {
        int t = __shfl_up_sync(0xFFFFFFFFu, x, o);
        if (lane >= o) x += t;
    }
    if (lane == 31) ws[wid] = x;
    __syncthreads();
    if (wid == 0) {
        int y = (lane < (blockDim.x >> 5)) ? ws[lane] : 0;
        #pragma unroll
        for (int o = 1; o < 32; o <<= 1) {
            int t = __shfl_up_sync(0xFFFFFFFFu, y, o);
            if (lane >= o) y += t;
        }
        ws[lane] = y;
    }
    __syncthreads();
    return x + (wid ? ws[wid - 1] : 0);
}

// Block-local scan + atomic base grab: CSR only needs disjoint contiguous
// slices per row, not globally ordered offsets.
__global__ void k_scan() {
    __shared__ int ws[32];
    __shared__ int s_base;
    int gid = blockIdx.x * SCAN_BLK + threadIdx.x;
    int v = (gid < NNODES) ? g_count[gid] : 0;
    int incl = block_incl_scan(v, ws);
    if (threadIdx.x == SCAN_BLK - 1) s_base = atomicAdd(&g_total, incl);
    __syncthreads();
    if (gid < NNODES) {
        int o = s_base + incl - v;
        g_off[gid]    = o;
        g_cursor[gid] = o;
    }
}

__global__ void k_scatter(const int* __restrict__ idx,
                          const int* __restrict__ ptype) {
    int e = blockIdx.x * blockDim.x + threadIdx.x;
    if (e >= NEDGES) return;
    int row = idx[e];
    int pos = atomicAdd(&g_cursor[row], 1);
    g_erow[pos] = row;
    g_ecol[pos] = idx[NEDGES + e] | (ptype[e] << 19);   // col < 2^19, pt < 16
}

// ---------------------------------------------------------------------------
// Layer-0 layernorm: half-warp per row, float4 lanes.
//   g_yA = LN(concat(ue, ie));  out = concat(ue, ie)   (emb0 seed)
__global__ void __launch_bounds__(256) k_ln0(const float* __restrict__ ue,
                                             const float* __restrict__ ie,
                                             float* __restrict__ out) {
    int tid  = blockIdx.x * blockDim.x + threadIdx.x;
    int row  = tid >> 4;
    int lane = threadIdx.x & 15;
    if (row >= NNODES) return;

    const float* src = (row < NUSERS)
        ? ue + (size_t)row * HID
        : ie + (size_t)(row - NUSERS) * HID;
    float4 v = ((const float4*)src)[lane];

    float s  = v.x + v.y + v.z + v.w;
    float sq = v.x * v.x + v.y * v.y + v.z * v.z + v.w * v.w;
    #pragma unroll
    for (int o = 8; o; o >>= 1) {
        s  += __shfl_xor_sync(0xFFFFFFFFu, s,  o);
        sq += __shfl_xor_sync(0xFFFFFFFFu, sq, o);
    }
    float mu  = s * (1.0f / HID);
    float var = sq * (1.0f / HID) - mu * mu;
    float r   = rsqrtf(var + LN_EPS);

    float4 o4;
    o4.x = (v.x - mu) * r;
    o4.y = (v.y - mu) * r;
    o4.z = (v.z - mu) * r;
    o4.w = (v.w - mu) * r;
    ((float4*)(g_yA + (size_t)row * HID))[lane] = o4;
    ((float4*)(out  + (size_t)row * HID))[lane] = v;
}

// ---------------------------------------------------------------------------
// Edge-parallel score: half-warp per sorted edge; no loops, no divergence.
//   g_e0[pos] = exp(dot(y[r],y[c])/8 + exp(lam)*dot(eig[r],eig[c]))
// (Softmax max-shift dropped: ratio shift-invariant, magnitudes f32-safe.)
__global__ void __launch_bounds__(256) k_score(const float* __restrict__ y,
                                               const float* __restrict__ eigs,
                                               const float* __restrict__ lam_l) {
    int tid  = blockIdx.x * blockDim.x + threadIdx.x;
    int pos  = tid >> 4;
    int lane = threadIdx.x & 15;
    if (pos >= NEDGES) return;

    int r = g_erow[pos];                       // broadcast load
    int c = g_ecol[pos] & 0x7FFFF;

    float4 yr = ((const float4*)(y + (size_t)r * HID))[lane];
    float4 yc = ((const float4*)(y + (size_t)c * HID))[lane];
    float  er = eigs[(size_t)r * EIG + lane];  // EIG == 16 lanes
    float  ec = eigs[(size_t)c * EIG + lane];
    float elam = expf(lam_l[0]);

    float part = (yr.x * yc.x + yr.y * yc.y + yr.z * yc.z + yr.w * yc.w) * 0.125f
               + elam * er * ec;
    #pragma unroll
    for (int o = 8; o; o >>= 1)
        part += __shfl_xor_sync(0xFFFFFFFFu, part, o);

    if (lane == 0) g_e0[pos] = expf(part);
}

// ---------------------------------------------------------------------------
// Row-parallel aggregation, half-warp per row, single y[c] gather per edge.
// Linearity: res = 0.5*(Σe0·y[c])/Σe0 + 0.5*(Σep·y[c])/Σep — denominators
// accumulated inline, no separate pass.
//   final==0 : out += res ; ydst = LN(res)  (next layer's y)
//   final==1 : out = (out + res) / 3
__global__ void __launch_bounds__(256) k_agg(const float* __restrict__ ysrc,
                                             float* __restrict__ ydst,
                                             const float* __restrict__ pemb,
                                             float* __restrict__ out,
                                             int final_mode) {
    __shared__ float s_ep[NPATHS];
    if (threadIdx.x < NPATHS) s_ep[threadIdx.x] = expf(pemb[threadIdx.x]);
    __syncthreads();

    int tid  = blockIdx.x * blockDim.x + threadIdx.x;
    int row  = tid >> 4;
    int lane = threadIdx.x & 15;
    if (row >= NNODES) return;

    int start = g_off[row];
    int end   = start + g_count[row];

    float4 acc0 = make_float4(0.f, 0.f, 0.f, 0.f);
    float4 acc1 = make_float4(0.f, 0.f, 0.f, 0.f);
    float  den0 = 0.0f, den1 = 0.0f;

    #pragma unroll 2
    for (int pos = start; pos < end; ++pos) {
        int packed = g_ecol[pos];              // broadcast
        int c   = packed & 0x7FFFF;
        float e0 = g_e0[pos];                  // broadcast
        float ep = s_ep[packed >> 19];
        float4 yc = ((const float4*)(ysrc + (size_t)c * HID))[lane];
        den0 += e0;  den1 += ep;
        acc0.x += e0 * yc.x;  acc0.y += e0 * yc.y;
        acc0.z += e0 * yc.z;  acc0.w += e0 * yc.w;
        acc1.x += ep * yc.x;  acc1.y += ep * yc.y;
        acc1.z += ep * yc.z;  acc1.w += ep * yc.w;
    }

    float4 res = make_float4(0.f, 0.f, 0.f, 0.f);
    if (end > start) {
        float i0 = 0.5f / den0;
        float i1 = 0.5f / den1;
        res.x = acc0.x * i0 + acc1.x * i1;
        res.y = acc0.y * i0 + acc1.y * i1;
        res.z = acc0.z * i0 + acc1.z * i1;
        res.w = acc0.w * i0 + acc1.w * i1;
    }

    float4* op = (float4*)(out + (size_t)row * HID);
    if (final_mode) {
        float4 cur = op[lane];
        cur.x = (cur.x + res.x) * (1.0f / 3.0f);
        cur.y = (cur.y + res.y) * (1.0f / 3.0f);
        cur.z = (cur.z + res.z) * (1.0f / 3.0f);
        cur.w = (cur.w + res.w) * (1.0f / 3.0f);
        op[lane] = cur;
    } else {
        float4 cur = op[lane];
        cur.x += res.x; cur.y += res.y; cur.z += res.z; cur.w += res.w;
        op[lane] = cur;

        // LN(res) -> ydst for next layer (epilogue only; not in edge loop)
        float s  = res.x + res.y + res.z + res.w;
        float sq = res.x * res.x + res.y * res.y + res.z * res.z + res.w * res.w;
        #pragma unroll
        for (int o = 8; o; o >>= 1) {
            s  += __shfl_xor_sync(0xFFFFFFFFu, s,  o);
            sq += __shfl_xor_sync(0xFFFFFFFFu, sq, o);
        }
        float mu  = s * (1.0f / HID);
        float var = sq * (1.0f / HID) - mu * mu;
        float rr  = rsqrtf(var + LN_EPS);
        float4 o4;
        o4.x = (res.x - mu) * rr;
        o4.y = (res.y - mu) * rr;
        o4.z = (res.z - mu) * rr;
        o4.w = (res.w - mu) * rr;
        ((float4*)(ydst + (size_t)row * HID))[lane] = o4;
    }
}

// ---------------------------------------------------------------------------
extern "C" void kernel_launch(void* const* d_in, const int* in_sizes, int n_in,
                              void* d_out, int out_size) {
    const float* ue   = (const float*)d_in[0];
    const float* ie   = (const float*)d_in[1];
    const float* eigs = (const float*)d_in[2];
    const float* lam  = (const float*)d_in[3];
    const float* pw   = (const float*)d_in[4];
    const int*   idx  = (const int*)d_in[5];
    const int*   pt   = (const int*)d_in[6];
    float*       out  = (float*)d_out;

    float *yA, *yB;
    cudaGetSymbolAddress((void**)&yA, g_yA);
    cudaGetSymbolAddress((void**)&yB, g_yB);

    const int edge_grid  = (NEDGES + 255) / 256;
    const int node_grid  = (NNODES + 255) / 256;
    const int half_grid  = ((NNODES * 16) + 255) / 256;   // half-warp per row
    const int score_grid = ((NEDGES * 16) + 255) / 256;   // half-warp per edge

    // CSR build (shared by both layers)
    k_zero   <<<node_grid, 256>>>();
    k_count  <<<edge_grid, 256>>>(idx);
    k_scan   <<<NBLK1, SCAN_BLK>>>();
    k_scatter<<<edge_grid, 256>>>(idx, pt);

    // layer 0: yA -> score -> agg (out += emb1, yB = LN(emb1))
    k_ln0  <<<half_grid, 256>>>(ue, ie, out);
    k_score<<<score_grid, 256>>>(yA, eigs, lam + 0);
    k_agg  <<<half_grid, 256>>>(yA, yB, pw + 0 * NPATHS, out, 0);

    // layer 1: yB -> score -> agg -> out = (out + emb2)/3
    k_score<<<score_grid, 256>>>(yB, eigs, lam + 1);
    k_agg  <<<half_grid, 256>>>(yB, yA, pw + 1 * NPATHS, out, 1);
}

// round 10
// speedup vs baseline: 1.1393x; 1.0236x over previous
#include <cuda_runtime.h>
#include <cuda_fp16.h>

#define NUSERS  100000
#define NNODES  300000
#define NEDGES  1250000
#define HID     64
#define EIG     16
#define NPATHS  14
#define LN_EPS  1e-5f

#define SCAN_BLK 1024
#define NBLK1    ((NNODES + SCAN_BLK - 1) / SCAN_BLK)   // 293

// ---------------- scratch (device globals: no allocation allowed) ----------
__device__ float  g_yA[(size_t)NNODES * HID];    // f32 layernormed emb (L0)
__device__ float  g_yB[(size_t)NNODES * HID];    // f32 layernormed emb (L1)
__device__ __half g_hA[(size_t)NNODES * HID];    // fp16 copy for score (L0)
__device__ __half g_hB[(size_t)NNODES * HID];    // fp16 copy for score (L1)
__device__ int2   g_edge[NEDGES];                // {row, col|pt<<19} sorted by row
__device__ float  g_e0[NEDGES];                  // exp(s0) per sorted edge
__device__ int    g_count[NNODES];               // row degree
__device__ int    g_off[NNODES];                 // CSR row offsets
__device__ int    g_cursor[NNODES];              // scatter cursors
__device__ int    g_total;                       // scan base allocator

// ---------------------------------------------------------------------------
__device__ __forceinline__ void store_h4(__half* hbase, int row, int lane, float4 v) {
    union { uint2 u; __half2 h[2]; } pk;
    pk.h[0] = __floats2half2_rn(v.x, v.y);
    pk.h[1] = __floats2half2_rn(v.z, v.w);
    ((uint2*)(hbase + (size_t)row * HID))[lane] = pk.u;
}

// ---------------------------------------------------------------------------
// Layer-0 layernorm: half-warp per row, float4 lanes. Runs FIRST; also zeroes
// the CSR histogram (no dependency on CSR kernels).
//   g_yA/g_hA = LN(concat(ue, ie));  out = concat(ue, ie)   (emb0 seed)
__global__ void __launch_bounds__(256) k_ln0(const float* __restrict__ ue,
                                             const float* __restrict__ ie,
                                             float* __restrict__ out) {
    int tid  = blockIdx.x * blockDim.x + threadIdx.x;
    int row  = tid >> 4;
    int lane = threadIdx.x & 15;
    if (row >= NNODES) return;

    if (lane == 0) g_count[row] = 0;
    if (tid == 0)  g_total = 0;

    const float* src = (row < NUSERS)
        ? ue + (size_t)row * HID
        : ie + (size_t)(row - NUSERS) * HID;
    float4 v = ((const float4*)src)[lane];

    float s  = v.x + v.y + v.z + v.w;
    float sq = v.x * v.x + v.y * v.y + v.z * v.z + v.w * v.w;
    #pragma unroll
    for (int o = 8; o; o >>= 1) {
        s  += __shfl_xor_sync(0xFFFFFFFFu, s,  o);
        sq += __shfl_xor_sync(0xFFFFFFFFu, sq, o);
    }
    float mu  = s * (1.0f / HID);
    float var = sq * (1.0f / HID) - mu * mu;
    float r   = rsqrtf(var + LN_EPS);

    float4 o4;
    o4.x = (v.x - mu) * r;
    o4.y = (v.y - mu) * r;
    o4.z = (v.z - mu) * r;
    o4.w = (v.w - mu) * r;
    ((float4*)(g_yA + (size_t)row * HID))[lane] = o4;
    store_h4(g_hA, row, lane, o4);
    ((float4*)(out + (size_t)row * HID))[lane] = v;
}

// ------------------------------ CSR build ----------------------------------
__global__ void k_count(const int* __restrict__ idx) {
    int e = blockIdx.x * blockDim.x + threadIdx.x;
    if (e < NEDGES) atomicAdd(&g_count[idx[e]], 1);
}

__device__ __forceinline__ int block_incl_scan(int v, int* ws) {
    int lane = threadIdx.x & 31, wid = threadIdx.x >> 5;
    int x = v;
    #pragma unroll
    for (int o = 1; o < 32; o <<= 1) {
        int t = __shfl_up_sync(0xFFFFFFFFu, x, o);
        if (lane >= o) x += t;
    }
    if (lane == 31) ws[wid] = x;
    __syncthreads();
    if (wid == 0) {
        int y = (lane < (blockDim.x >> 5)) ? ws[lane] : 0;
        #pragma unroll
        for (int o = 1; o < 32; o <<= 1) {
            int t = __shfl_up_sync(0xFFFFFFFFu, y, o);
            if (lane >= o) y += t;
        }
        ws[lane] = y;
    }
    __syncthreads();
    return x + (wid ? ws[wid - 1] : 0);
}

// Block-local scan + atomic base grab: CSR only needs disjoint contiguous
// slices per row, not globally ordered offsets.
__global__ void k_scan() {
    __shared__ int ws[32];
    __shared__ int s_base;
    int gid = blockIdx.x * SCAN_BLK + threadIdx.x;
    int v = (gid < NNODES) ? g_count[gid] : 0;
    int incl = block_incl_scan(v, ws);
    if (threadIdx.x == SCAN_BLK - 1) s_base = atomicAdd(&g_total, incl);
    __syncthreads();
    if (gid < NNODES) {
        int o = s_base + incl - v;
        g_off[gid]    = o;
        g_cursor[gid] = o;
    }
}

__global__ void k_scatter(const int* __restrict__ idx,
                          const int* __restrict__ ptype) {
    int e = blockIdx.x * blockDim.x + threadIdx.x;
    if (e >= NEDGES) return;
    int row = idx[e];
    int pos = atomicAdd(&g_cursor[row], 1);
    g_edge[pos] = make_int2(row, idx[NEDGES + e] | (ptype[e] << 19));
}

// ---------------------------------------------------------------------------
// Edge-parallel score: half-warp per sorted edge; fp16 y, f32 eigs.
//   g_e0[pos] = exp(dot(y[r],y[c])/8 + exp(lam)*dot(eig[r],eig[c]))
// (Softmax max-shift dropped: ratio shift-invariant, magnitudes f32-safe.)
__global__ void __launch_bounds__(256) k_score(const __half* __restrict__ hy,
                                               const float* __restrict__ eigs,
                                               const float* __restrict__ lam_l) {
    int tid  = blockIdx.x * blockDim.x + threadIdx.x;
    int pos  = tid >> 4;
    int lane = threadIdx.x & 15;
    if (pos >= NEDGES) return;

    int2 ed = g_edge[pos];                     // 8B broadcast load
    int r = ed.x;
    int c = ed.y & 0x7FFFF;

    uint2 ur = ((const uint2*)(hy + (size_t)r * HID))[lane];
    uint2 uc = ((const uint2*)(hy + (size_t)c * HID))[lane];
    float  er = eigs[(size_t)r * EIG + lane];  // EIG == 16 lanes
    float  ec = eigs[(size_t)c * EIG + lane];
    float elam = expf(lam_l[0]);

    float2 ra = __half22float2(*(const __half2*)&ur.x);
    float2 rb = __half22float2(*(const __half2*)&ur.y);
    float2 ca = __half22float2(*(const __half2*)&uc.x);
    float2 cb = __half22float2(*(const __half2*)&uc.y);

    float part = (ra.x * ca.x + ra.y * ca.y + rb.x * cb.x + rb.y * cb.y) * 0.125f
               + elam * er * ec;
    #pragma unroll
    for (int o = 8; o; o >>= 1)
        part += __shfl_xor_sync(0xFFFFFFFFu, part, o);

    if (lane == 0) g_e0[pos] = expf(part);
}

// ---------------------------------------------------------------------------
// Row-parallel aggregation, half-warp per row, single f32 y[c] gather/edge.
// Linearity: res = 0.5*(Σe0·y[c])/Σe0 + 0.5*(Σep·y[c])/Σep.
//   final==0 : out += res ; ydst/hdst = LN(res)  (next layer's y)
//   final==1 : out = (out + res) / 3
__global__ void __launch_bounds__(256) k_agg(const float* __restrict__ ysrc,
                                             float* __restrict__ ydst,
                                             __half* __restrict__ hdst,
                                             const float* __restrict__ pemb,
                                             float* __restrict__ out,
                                             int final_mode) {
    __shared__ float s_ep[NPATHS];
    if (threadIdx.x < NPATHS) s_ep[threadIdx.x] = expf(pemb[threadIdx.x]);
    __syncthreads();

    int tid  = blockIdx.x * blockDim.x + threadIdx.x;
    int row  = tid >> 4;
    int lane = threadIdx.x & 15;
    if (row >= NNODES) return;

    int start = g_off[row];
    int end   = start + g_count[row];

    float4 acc0 = make_float4(0.f, 0.f, 0.f, 0.f);
    float4 acc1 = make_float4(0.f, 0.f, 0.f, 0.f);
    float  den0 = 0.0f, den1 = 0.0f;

    #pragma unroll 4
    for (int pos = start; pos < end; ++pos) {
        int   packed = g_edge[pos].y;          // broadcast
        int   c  = packed & 0x7FFFF;
        float e0 = g_e0[pos];                  // broadcast
        float ep = s_ep[packed >> 19];
        float4 yc = ((const float4*)(ysrc + (size_t)c * HID))[lane];
        den0 += e0;  den1 += ep;
        acc0.x += e0 * yc.x;  acc0.y += e0 * yc.y;
        acc0.z += e0 * yc.z;  acc0.w += e0 * yc.w;
        acc1.x += ep * yc.x;  acc1.y += ep * yc.y;
        acc1.z += ep * yc.z;  acc1.w += ep * yc.w;
    }

    float4 res = make_float4(0.f, 0.f, 0.f, 0.f);
    if (end > start) {
        float i0 = 0.5f / den0;
        float i1 = 0.5f / den1;
        res.x = acc0.x * i0 + acc1.x * i1;
        res.y = acc0.y * i0 + acc1.y * i1;
        res.z = acc0.z * i0 + acc1.z * i1;
        res.w = acc0.w * i0 + acc1.w * i1;
    }

    float4* op = (float4*)(out + (size_t)row * HID);
    if (final_mode) {
        float4 cur = op[lane];
        cur.x = (cur.x + res.x) * (1.0f / 3.0f);
        cur.y = (cur.y + res.y) * (1.0f / 3.0f);
        cur.z = (cur.z + res.z) * (1.0f / 3.0f);
        cur.w = (cur.w + res.w) * (1.0f / 3.0f);
        op[lane] = cur;
    } else {
        float4 cur = op[lane];
        cur.x += res.x; cur.y += res.y; cur.z += res.z; cur.w += res.w;
        op[lane] = cur;

        // LN(res) -> ydst/hdst for next layer (epilogue only)
        float s  = res.x + res.y + res.z + res.w;
        float sq = res.x * res.x + res.y * res.y + res.z * res.z + res.w * res.w;
        #pragma unroll
        for (int o = 8; o; o >>= 1) {
            s  += __shfl_xor_sync(0xFFFFFFFFu, s,  o);
            sq += __shfl_xor_sync(0xFFFFFFFFu, sq, o);
        }
        float mu  = s * (1.0f / HID);
        float var = sq * (1.0f / HID) - mu * mu;
        float rr  = rsqrtf(var + LN_EPS);
        float4 o4;
        o4.x = (res.x - mu) * rr;
        o4.y = (res.y - mu) * rr;
        o4.z = (res.z - mu) * rr;
        o4.w = (res.w - mu) * rr;
        ((float4*)(ydst + (size_t)row * HID))[lane] = o4;
        store_h4(hdst, row, lane, o4);
    }
}

// ---------------------------------------------------------------------------
extern "C" void kernel_launch(void* const* d_in, const int* in_sizes, int n_in,
                              void* d_out, int out_size) {
    const float* ue   = (const float*)d_in[0];
    const float* ie   = (const float*)d_in[1];
    const float* eigs = (const float*)d_in[2];
    const float* lam  = (const float*)d_in[3];
    const float* pw   = (const float*)d_in[4];
    const int*   idx  = (const int*)d_in[5];
    const int*   pt   = (const int*)d_in[6];
    float*       out  = (float*)d_out;

    float *yA, *yB;
    __half *hA, *hB;
    cudaGetSymbolAddress((void**)&yA, g_yA);
    cudaGetSymbolAddress((void**)&yB, g_yB);
    cudaGetSymbolAddress((void**)&hA, g_hA);
    cudaGetSymbolAddress((void**)&hB, g_hB);

    const int edge_grid  = (NEDGES + 255) / 256;
    const int half_grid  = ((NNODES * 16) + 255) / 256;   // half-warp per row
    const int score_grid = ((NEDGES * 16) + 255) / 256;   // half-warp per edge

    // ln0 first (also zeroes CSR histogram), then CSR build
    k_ln0    <<<half_grid, 256>>>(ue, ie, out);
    k_count  <<<edge_grid, 256>>>(idx);
    k_scan   <<<NBLK1, SCAN_BLK>>>();
    k_scatter<<<edge_grid, 256>>>(idx, pt);

    // layer 0: score(fp16 yA) -> agg(f32 yA) ; out += emb1, yB/hB = LN(emb1)
    k_score<<<score_grid, 256>>>(hA, eigs, lam + 0);
    k_agg  <<<half_grid, 256>>>(yA, yB, hB, pw + 0 * NPATHS, out, 0);

    // layer 1: score(fp16 yB) -> agg(f32 yB) -> out = (out + emb2)/3
    k_score<<<score_grid, 256>>>(hB, eigs, lam + 1);
    k_agg  <<<half_grid, 256>>>(yB, yA, hA, pw + 1 * NPATHS, out, 1);
}

// round 12
// speedup vs baseline: 1.2201x; 1.0710x over previous
#include <cuda_runtime.h>
#include <cuda_fp16.h>

#define NUSERS  100000
#define NNODES  300000
#define NEDGES  1250000
#define HID     64
#define EIG     16
#define NPATHS  14
#define LN_EPS  1e-5f

#define SCAN_BLK 1024
#define NBLK1    ((NNODES + SCAN_BLK - 1) / SCAN_BLK)   // 293
#define NHALF    (NEDGES / 2)                            // 625000 (even)

// ---------------- scratch (device globals: no allocation allowed) ----------
__device__ float  g_yA[(size_t)NNODES * HID];    // f32 layernormed emb (L0)
__device__ float  g_yB[(size_t)NNODES * HID];    // f32 layernormed emb (L1)
__device__ __half g_hA[(size_t)NNODES * HID];    // fp16 copy for score (L0)
__device__ __half g_hB[(size_t)NNODES * HID];    // fp16 copy for score (L1)
__device__ int2   g_edge[NEDGES];                // {row, col|pt<<19} sorted by row
__device__ float  g_yeig[NEDGES];                // dot(eig[r],eig[c]) per edge
__device__ float  g_e0[NEDGES];                  // exp(s0) per sorted edge
__device__ int    g_count[NNODES];               // row degree
__device__ int    g_off[NNODES];                 // CSR row offsets
__device__ int    g_cursor[NNODES];              // scatter cursors
__device__ int    g_total;                       // scan base allocator

// ---------------------------------------------------------------------------
__device__ __forceinline__ void store_h4(__half* hbase, int row, int lane, float4 v) {
    union { uint2 u; __half2 h[2]; } pk;
    pk.h[0] = __floats2half2_rn(v.x, v.y);
    pk.h[1] = __floats2half2_rn(v.z, v.w);
    ((uint2*)(hbase + (size_t)row * HID))[lane] = pk.u;
}

// ---------------------------------------------------------------------------
// Layer-0 layernorm: half-warp per row, float4 lanes. Runs FIRST; also zeroes
// the CSR histogram.  g_yA/g_hA = LN(concat(ue,ie)); out = concat(ue,ie)
__global__ void __launch_bounds__(256) k_ln0(const float* __restrict__ ue,
                                             const float* __restrict__ ie,
                                             float* __restrict__ out) {
    int tid  = blockIdx.x * blockDim.x + threadIdx.x;
    int row  = tid >> 4;
    int lane = threadIdx.x & 15;
    if (row >= NNODES) return;

    if (lane == 0) g_count[row] = 0;
    if (tid == 0)  g_total = 0;

    const float* src = (row < NUSERS)
        ? ue + (size_t)row * HID
        : ie + (size_t)(row - NUSERS) * HID;
    float4 v = ((const float4*)src)[lane];

    float s  = v.x + v.y + v.z + v.w;
    float sq = v.x * v.x + v.y * v.y + v.z * v.z + v.w * v.w;
    #pragma unroll
    for (int o = 8; o; o >>= 1) {
        s  += __shfl_xor_sync(0xFFFFFFFFu, s,  o);
        sq += __shfl_xor_sync(0xFFFFFFFFu, sq, o);
    }
    float mu  = s * (1.0f / HID);
    float var = sq * (1.0f / HID) - mu * mu;
    float r   = rsqrtf(var + LN_EPS);

    float4 o4;
    o4.x = (v.x - mu) * r;
    o4.y = (v.y - mu) * r;
    o4.z = (v.z - mu) * r;
    o4.w = (v.w - mu) * r;
    ((float4*)(g_yA + (size_t)row * HID))[lane] = o4;
    store_h4(g_hA, row, lane, o4);
    ((float4*)(out + (size_t)row * HID))[lane] = v;
}

// ------------------------------ CSR build ----------------------------------
__global__ void k_count(const int* __restrict__ idx) {
    int e = blockIdx.x * blockDim.x + threadIdx.x;
    if (e < NEDGES) atomicAdd(&g_count[idx[e]], 1);
}

__device__ __forceinline__ int block_incl_scan(int v, int* ws) {
    int lane = threadIdx.x & 31, wid = threadIdx.x >> 5;
    int x = v;
    #pragma unroll
    for (int o = 1; o < 32; o <<= 1) {
        int t = __shfl_up_sync(0xFFFFFFFFu, x, o);
        if (lane >= o) x += t;
    }
    if (lane == 31) ws[wid] = x;
    __syncthreads();
    if (wid == 0) {
        int y = (lane < (blockDim.x >> 5)) ? ws[lane] : 0;
        #pragma unroll
        for (int o = 1; o < 32; o <<= 1) {
            int t = __shfl_up_sync(0xFFFFFFFFu, y, o);
            if (lane >= o) y += t;
        }
        ws[lane] = y;
    }
    __syncthreads();
    return x + (wid ? ws[wid - 1] : 0);
}

// Block-local scan + atomic base grab (CSR needs only disjoint slices).
__global__ void k_scan() {
    __shared__ int ws[32];
    __shared__ int s_base;
    int gid = blockIdx.x * SCAN_BLK + threadIdx.x;
    int v = (gid < NNODES) ? g_count[gid] : 0;
    int incl = block_incl_scan(v, ws);
    if (threadIdx.x == SCAN_BLK - 1) s_base = atomicAdd(&g_total, incl);
    __syncthreads();
    if (gid < NNODES) {
        int o = s_base + incl - v;
        g_off[gid]    = o;
        g_cursor[gid] = o;
    }
}

__global__ void k_scatter(const int* __restrict__ idx,
                          const int* __restrict__ ptype) {
    int e = blockIdx.x * blockDim.x + threadIdx.x;
    if (e >= NEDGES) return;
    int row = idx[e];
    int pos = atomicAdd(&g_cursor[row], 1);
    g_edge[pos] = make_int2(row, idx[NEDGES + e] | (ptype[e] << 19));
}

// ---------------------------------------------------------------------------
// Pre-pass: layer-independent eig dot per sorted edge, 2 edges per half-warp.
//   g_yeig[pos] = dot(eigs[row], eigs[col])      (EIG == 16 lanes)
__global__ void __launch_bounds__(256) k_prep(const float* __restrict__ eigs) {
    int tid  = blockIdx.x * blockDim.x + threadIdx.x;
    int h    = tid >> 4;
    int lane = threadIdx.x & 15;
    if (h >= NHALF) return;

    int2 ed0 = g_edge[2 * h];
    int2 ed1 = g_edge[2 * h + 1];

    float p0 = eigs[(size_t)ed0.x * EIG + lane] * eigs[(size_t)(ed0.y & 0x7FFFF) * EIG + lane];
    float p1 = eigs[(size_t)ed1.x * EIG + lane] * eigs[(size_t)(ed1.y & 0x7FFFF) * EIG + lane];
    #pragma unroll
    for (int o = 8; o; o >>= 1) {
        p0 += __shfl_xor_sync(0xFFFFFFFFu, p0, o);
        p1 += __shfl_xor_sync(0xFFFFFFFFu, p1, o);
    }
    if (lane == 0) ((float2*)g_yeig)[h] = make_float2(p0, p1);
}

// ---------------------------------------------------------------------------
// Edge-parallel score, 2 edges per half-warp (interleaved chains), fp16 y.
//   g_e0[pos] = exp(dot(y[r],y[c])/8 + exp(lam)*g_yeig[pos])
// (Softmax max-shift dropped: ratio shift-invariant, magnitudes f32-safe.)
__global__ void __launch_bounds__(256) k_score(const __half* __restrict__ hy,
                                               const float* __restrict__ lam_l) {
    int tid  = blockIdx.x * blockDim.x + threadIdx.x;
    int h    = tid >> 4;
    int lane = threadIdx.x & 15;
    if (h >= NHALF) return;

    int2 ed0 = g_edge[2 * h];
    int2 ed1 = g_edge[2 * h + 1];

    uint2 ur0 = ((const uint2*)(hy + (size_t)ed0.x * HID))[lane];
    uint2 uc0 = ((const uint2*)(hy + (size_t)(ed0.y & 0x7FFFF) * HID))[lane];
    uint2 ur1 = ((const uint2*)(hy + (size_t)ed1.x * HID))[lane];
    uint2 uc1 = ((const uint2*)(hy + (size_t)(ed1.y & 0x7FFFF) * HID))[lane];

    float2 a, b;
    float p0, p1;
    a = __half22float2(*(const __half2*)&ur0.x); b = __half22float2(*(const __half2*)&uc0.x);
    p0 = a.x * b.x + a.y * b.y;
    a = __half22float2(*(const __half2*)&ur0.y); b = __half22float2(*(const __half2*)&uc0.y);
    p0 += a.x * b.x + a.y * b.y;
    a = __half22float2(*(const __half2*)&ur1.x); b = __half22float2(*(const __half2*)&uc1.x);
    p1 = a.x * b.x + a.y * b.y;
    a = __half22float2(*(const __half2*)&ur1.y); b = __half22float2(*(const __half2*)&uc1.y);
    p1 += a.x * b.x + a.y * b.y;

    #pragma unroll
    for (int o = 8; o; o >>= 1) {
        p0 += __shfl_xor_sync(0xFFFFFFFFu, p0, o);
        p1 += __shfl_xor_sync(0xFFFFFFFFu, p1, o);
    }

    if (lane == 0) {
        float elam = __expf(lam_l[0]);
        float2 ye = ((const float2*)g_yeig)[h];
        float e00 = __expf(p0 * 0.125f + elam * ye.x);
        float e01 = __expf(p1 * 0.125f + elam * ye.y);
        ((float2*)g_e0)[h] = make_float2(e00, e01);
    }
}

// ---------------------------------------------------------------------------
// Row-parallel aggregation, half-warp per row, single f32 y[c] gather/edge.
// Linearity: res = 0.5*(Σe0·y[c])/Σe0 + 0.5*(Σep·y[c])/Σep.
//   final==0 : out += res ; ydst/hdst = LN(res)
//   final==1 : out = (out + res) / 3
__global__ void __launch_bounds__(256) k_agg(const float* __restrict__ ysrc,
                                             float* __restrict__ ydst,
                                             __half* __restrict__ hdst,
                                             const float* __restrict__ pemb,
                                             float* __restrict__ out,
                                             int final_mode) {
    __shared__ float s_ep[NPATHS];
    if (threadIdx.x < NPATHS) s_ep[threadIdx.x] = __expf(pemb[threadIdx.x]);
    __syncthreads();

    int tid  = blockIdx.x * blockDim.x + threadIdx.x;
    int row  = tid >> 4;
    int lane = threadIdx.x & 15;
    if (row >= NNODES) return;

    int start = g_off[row];
    int end   = start + g_count[row];

    float4 acc0 = make_float4(0.f, 0.f, 0.f, 0.f);
    float4 acc1 = make_float4(0.f, 0.f, 0.f, 0.f);
    float  den0 = 0.0f, den1 = 0.0f;

    #pragma unroll 4
    for (int pos = start; pos < end; ++pos) {
        int   packed = g_edge[pos].y;          // broadcast
        int   c  = packed & 0x7FFFF;
        float e0 = g_e0[pos];                  // broadcast
        float ep = s_ep[packed >> 19];
        float4 yc = ((const float4*)(ysrc + (size_t)c * HID))[lane];
        den0 += e0;  den1 += ep;
        acc0.x += e0 * yc.x;  acc0.y += e0 * yc.y;
        acc0.z += e0 * yc.z;  acc0.w += e0 * yc.w;
        acc1.x += ep * yc.x;  acc1.y += ep * yc.y;
        acc1.z += ep * yc.z;  acc1.w += ep * yc.w;
    }

    float4 res = make_float4(0.f, 0.f, 0.f, 0.f);
    if (end > start) {
        float i0 = 0.5f / den0;
        float i1 = 0.5f / den1;
        res.x = acc0.x * i0 + acc1.x * i1;
        res.y = acc0.y * i0 + acc1.y * i1;
        res.z = acc0.z * i0 + acc1.z * i1;
        res.w = acc0.w * i0 + acc1.w * i1;
    }

    float4* op = (float4*)(out + (size_t)row * HID);
    if (final_mode) {
        float4 cur = op[lane];
        cur.x = (cur.x + res.x) * (1.0f / 3.0f);
        cur.y = (cur.y + res.y) * (1.0f / 3.0f);
        cur.z = (cur.z + res.z) * (1.0f / 3.0f);
        cur.w = (cur.w + res.w) * (1.0f / 3.0f);
        op[lane] = cur;
    } else {
        float4 cur = op[lane];
        cur.x += res.x; cur.y += res.y; cur.z += res.z; cur.w += res.w;
        op[lane] = cur;

        // LN(res) -> ydst/hdst for next layer (epilogue only)
        float s  = res.x + res.y + res.z + res.w;
        float sq = res.x * res.x + res.y * res.y + res.z * res.z + res.w * res.w;
        #pragma unroll
        for (int o = 8; o; o >>= 1) {
            s  += __shfl_xor_sync(0xFFFFFFFFu, s,  o);
            sq += __shfl_xor_sync(0xFFFFFFFFu, sq, o);
        }
        float mu  = s * (1.0f / HID);
        float var = sq * (1.0f / HID) - mu * mu;
        float rr  = rsqrtf(var + LN_EPS);
        float4 o4;
        o4.x = (res.x - mu) * rr;
        o4.y = (res.y - mu) * rr;
        o4.z = (res.z - mu) * rr;
        o4.w = (res.w - mu) * rr;
        ((float4*)(ydst + (size_t)row * HID))[lane] = o4;
        store_h4(hdst, row, lane, o4);
    }
}

// ---------------------------------------------------------------------------
extern "C" void kernel_launch(void* const* d_in, const int* in_sizes, int n_in,
                              void* d_out, int out_size) {
    const float* ue   = (const float*)d_in[0];
    const float* ie   = (const float*)d_in[1];
    const float* eigs = (const float*)d_in[2];
    const float* lam  = (const float*)d_in[3];
    const float* pw   = (const float*)d_in[4];
    const int*   idx  = (const int*)d_in[5];
    const int*   pt   = (const int*)d_in[6];
    float*       out  = (float*)d_out;

    float *yA, *yB;
    __half *hA, *hB;
    cudaGetSymbolAddress((void**)&yA, g_yA);
    cudaGetSymbolAddress((void**)&yB, g_yB);
    cudaGetSymbolAddress((void**)&hA, g_hA);
    cudaGetSymbolAddress((void**)&hB, g_hB);

    const int edge_grid  = (NEDGES + 255) / 256;
    const int half_grid  = ((NNODES * 16) + 255) / 256;   // half-warp per row
    const int pair_grid  = ((NHALF * 16) + 255) / 256;    // half-warp per 2 edges

    // ln0 first (also zeroes CSR histogram), then CSR build + eig-dot prepass
    k_ln0    <<<half_grid, 256>>>(ue, ie, out);
    k_count  <<<edge_grid, 256>>>(idx);
    k_scan   <<<NBLK1, SCAN_BLK>>>();
    k_scatter<<<edge_grid, 256>>>(idx, pt);
    k_prep   <<<pair_grid, 256>>>(eigs);

    // layer 0: score(fp16 yA) -> agg(f32 yA) ; out += emb1, yB/hB = LN(emb1)
    k_score<<<pair_grid, 256>>>(hA, lam + 0);
    k_agg  <<<half_grid, 256>>>(yA, yB, hB, pw + 0 * NPATHS, out, 0);

    // layer 1: score(fp16 yB) -> agg(f32 yB) -> out = (out + emb2)/3
    k_score<<<pair_grid, 256>>>(hB, lam + 1);
    k_agg  <<<half_grid, 256>>>(yB, yA, hA, pw + 1 * NPATHS, out, 1);
}